// round 5
// baseline (speedup 1.0000x reference)
#include <cuda_runtime.h>
#include <math.h>
#include <stdint.h>

#define NWAY   64
#define NSHOT  5
#define NTOT   12800
#define NLAB   320
#define NUNL   12480
#define DIM    1536
#define NEPOCH 20
#define EPSF   1e-6f
#define MAXIT  1000
#define SGRID  148
#define RPCMAX 85
#define NDBLK  98        /* ceil(12480/128) blocks for distE */
#define KSPLIT 13
#define KCH    960       /* 13*960 = 12480 */
#define EM1F   1.7182818284590452f
#define DENF   523.59140914229523f   /* 315 + 5e + 195 */

/* ------------- device scratch (static; no allocations) ------------- */
static __device__ float    g_Z[NTOT * DIM];
static __device__ float    g_E[NUNL * NWAY];
static __device__ float    g_D[NUNL * NWAY];
static __device__ float    g_mus[NWAY * DIM];
static __device__ float    g_C[NWAY * DIM];
static __device__ float    g_SL[DIM];
static __device__ float    g_meanL[DIM];
static __device__ float    g_meanU[DIM];
static __device__ float    g_colpart[32 * 2 * DIM];
static __device__ float    g_musn[NWAY];
static __device__ float    g_Spart[NDBLK];
static __device__ float    g_u[NUNL];
static __device__ float    g_v[NWAY];
static __device__ float    g_cs[3 * SGRID * NWAY];
static __device__ unsigned g_maxd[3];
static __device__ float    g_pzpart[KSPLIT * NWAY * DIM];
static __device__ int      g_acc;
static __device__ unsigned g_barcnt = 0;
static __device__ unsigned g_bargen = 0;

/* ------------- reduction helpers ------------- */
__device__ __forceinline__ float warpSum(float x) {
#pragma unroll
    for (int o = 16; o > 0; o >>= 1) x += __shfl_down_sync(0xffffffffu, x, o);
    return x;
}
__device__ __forceinline__ float warpMax(float x) {
#pragma unroll
    for (int o = 16; o > 0; o >>= 1) x = fmaxf(x, __shfl_down_sync(0xffffffffu, x, o));
    return x;
}
__device__ __forceinline__ float blockSum256(float x) {
    __shared__ float s[8];
    int ln = threadIdx.x & 31, w = threadIdx.x >> 5;
    x = warpSum(x);
    if (ln == 0) s[w] = x;
    __syncthreads();
    if (w == 0) {
        float y = (ln < 8) ? s[ln] : 0.f;
        y = warpSum(y);
        if (ln == 0) s[0] = y;
    }
    __syncthreads();
    float r = s[0];
    __syncthreads();
    return r;
}
__device__ __forceinline__ float blockMax256(float x) {
    __shared__ float s[8];
    int ln = threadIdx.x & 31, w = threadIdx.x >> 5;
    x = warpMax(x);
    if (ln == 0) s[w] = x;
    __syncthreads();
    if (w == 0) {
        float y = (ln < 8) ? s[ln] : 0.f;
        y = warpMax(y);
        if (ln == 0) s[0] = y;
    }
    __syncthreads();
    float r = s[0];
    __syncthreads();
    return r;
}

/* grid-wide barrier; all SGRID CTAs resident (grid == SGRID <= #SMs) */
__device__ __forceinline__ void gridbar() {
    __syncthreads();
    if (threadIdx.x == 0) {
        __threadfence();
        unsigned g = atomicAdd(&g_bargen, 0u);
        if (atomicAdd(&g_barcnt, 1u) == (unsigned)(SGRID - 1)) {
            atomicExch(&g_barcnt, 0u);
            __threadfence();
            atomicAdd(&g_bargen, 1u);
        } else {
            while (atomicAdd(&g_bargen, 0u) == g) { __nanosleep(64); }
        }
        __threadfence();
    }
    __syncthreads();
}

/* ------------- setup / preprocessing ------------- */
__global__ void k_setup() {
    if (threadIdx.x == 0) g_acc = 0;
}

/* z = l2norm(sqrt(x + 1e-6)) per row */
__global__ void __launch_bounds__(256) k_pownorm(const float* __restrict__ X) {
    int r = blockIdx.x, t = threadIdx.x;
    const float* xr = X + (size_t)r * DIM;
    float* zr = g_Z + (size_t)r * DIM;
    float v[6];
    float ss = 0.f;
#pragma unroll
    for (int k = 0; k < 6; k++) {
        float x = sqrtf(xr[t + 256 * k] + 1e-6f);
        v[k] = x;
        ss += x * x;
    }
    float tot = blockSum256(ss);
    float inv = 1.0f / fmaxf(sqrtf(tot), 1e-12f);
#pragma unroll
    for (int k = 0; k < 6; k++) zr[t + 256 * k] = v[k] * inv;
}

/* deterministic column-sum partials: grid (6, 32), 400-row chunks */
__global__ void __launch_bounds__(256) k_colpart() {
    int c = blockIdx.x * 256 + threadIdx.x;
    int r0 = blockIdx.y * 400;
    float sL = 0.f, sU = 0.f;
    for (int r = r0; r < r0 + 400; r++) {
        float x = g_Z[(size_t)r * DIM + c];
        if (r < NLAB) sL += x; else sU += x;
    }
    g_colpart[(blockIdx.y * 2 + 0) * DIM + c] = sL;
    g_colpart[(blockIdx.y * 2 + 1) * DIM + c] = sU;
}

__global__ void __launch_bounds__(256) k_colreduce() {
    int c = blockIdx.x * 256 + threadIdx.x;
    float sL = 0.f, sU = 0.f;
    for (int b = 0; b < 32; b++) {
        sL += g_colpart[(b * 2 + 0) * DIM + c];
        sU += g_colpart[(b * 2 + 1) * DIM + c];
    }
    g_meanL[c] = sL * (1.0f / (float)NLAB);
    g_meanU[c] = sU * (1.0f / (float)NUNL);
}

/* subtract group mean, l2-normalize */
__global__ void __launch_bounds__(256) k_centernorm() {
    int r = blockIdx.x, t = threadIdx.x;
    float* zr = g_Z + (size_t)r * DIM;
    float v[6];
    float ss = 0.f;
#pragma unroll
    for (int k = 0; k < 6; k++) {
        int d = t + 256 * k;
        float m = (r < NLAB) ? g_meanL[d] : g_meanU[d];
        float x = zr[d] - m;
        v[k] = x;
        ss += x * x;
    }
    float tot = blockSum256(ss);
    float inv = 1.0f / fmaxf(sqrtf(tot), 1e-12f);
#pragma unroll
    for (int k = 0; k < 6; k++) zr[t + 256 * k] = v[k] * inv;
}

/* C_j = sum of 5 labeled shots of class j; mus = C/5 */
__global__ void __launch_bounds__(256) k_initmus() {
    int j = blockIdx.x, t = threadIdx.x;
#pragma unroll
    for (int k = 0; k < 6; k++) {
        int d = t + 256 * k;
        float s = 0.f;
#pragma unroll
        for (int s5 = 0; s5 < 5; s5++) s += g_Z[(size_t)(s5 * NWAY + j) * DIM + d];
        g_C[j * DIM + d] = s;
        g_mus[j * DIM + d] = s * 0.2f;
    }
}

__global__ void __launch_bounds__(256) k_SL() {
    int c = blockIdx.x * 256 + threadIdx.x;
    float s = 0.f;
    for (int r = 0; r < NLAB; r++) s += g_Z[(size_t)r * DIM + c];
    g_SL[c] = s;
}

/* ------------- per-epoch kernels ------------- */
__global__ void __launch_bounds__(256) k_musnorm() {
    int j = blockIdx.x, t = threadIdx.x;
    float s = 0.f;
#pragma unroll
    for (int k = 0; k < 6; k++) {
        float m = g_mus[j * DIM + t + 256 * k];
        s += m * m;
    }
    float tot = blockSum256(s);
    if (t == 0) g_musn[j] = tot;
}

/* G = Z_u · mus^T -> dist -> E = exp(-10 d); per-block partial of sum(E) */
__global__ void __launch_bounds__(256) k_distE() {
    __shared__ float As[32 * 129];
    __shared__ float Bs[64 * 33];
    __shared__ float musnS[64];
    int t = threadIdx.x;
    int rbase = blockIdx.x * 128;
    if (t < 64) musnS[t] = g_musn[t];
    int ty = t >> 4, tx = t & 15;
    float acc[8][4];
#pragma unroll
    for (int i = 0; i < 8; i++)
#pragma unroll
        for (int ii = 0; ii < 4; ii++) acc[i][ii] = 0.f;

    for (int kb = 0; kb < DIM; kb += 32) {
        __syncthreads();
#pragma unroll
        for (int l = 0; l < 16; l++) {
            int idx = t + l * 256;
            int k = idx & 31, m = idx >> 5;
            int r = rbase + m;
            As[k * 129 + m] = (r < NUNL) ? g_Z[(size_t)(NLAB + r) * DIM + kb + k] : 0.f;
        }
#pragma unroll
        for (int l = 0; l < 8; l++) {
            int idx = t + l * 256;
            int k = idx & 31, n = idx >> 5;
            Bs[n * 33 + k] = g_mus[n * DIM + kb + k];
        }
        __syncthreads();
#pragma unroll
        for (int k = 0; k < 32; k++) {
            float a[8], b[4];
#pragma unroll
            for (int i = 0; i < 8; i++) a[i] = As[k * 129 + ty * 8 + i];
#pragma unroll
            for (int ii = 0; ii < 4; ii++) b[ii] = Bs[(tx * 4 + ii) * 33 + k];
#pragma unroll
            for (int i = 0; i < 8; i++)
#pragma unroll
                for (int ii = 0; ii < 4; ii++) acc[i][ii] += a[i] * b[ii];
        }
    }
    __syncthreads();
    float ls = 0.f;
#pragma unroll
    for (int i = 0; i < 8; i++) {
        int r = rbase + ty * 8 + i;
        if (r < NUNL) {
#pragma unroll
            for (int ii = 0; ii < 4; ii++) {
                int j = tx * 4 + ii;
                float d2 = 1.0f + musnS[j] - 2.0f * acc[i][ii];
                float dd = sqrtf(fmaxf(d2, 0.f));
                float e = expf(-10.0f * dd);
                g_D[(size_t)r * NWAY + j] = dd;
                g_E[(size_t)r * NWAY + j] = e;
                ls += e;
            }
        }
    }
    float sp = blockSum256(ls);
    if (t == 0) g_Spart[blockIdx.x] = sp;
}

/* persistent Sinkhorn: one grid barrier per iteration, 3-buffer rotation */
__global__ void __launch_bounds__(256) k_sinkhorn() {
    __shared__ float Es[RPCMAX * 65];
    __shared__ float vs[64];
    __shared__ float wloc[RPCMAX];
    __shared__ float uprev[RPCMAX];
    __shared__ float wcand[RPCMAX];
    __shared__ float rowsv[RPCMAX];
    __shared__ float cred[256];
    __shared__ float sS;
    __shared__ int   sBrk;

    int c = blockIdx.x, tid = threadIdx.x;
    int r0 = (c * NUNL) / SGRID;
    int r1 = ((c + 1) * NUNL) / SGRID;
    int nr = r1 - r0;

    for (int idx = tid; idx < nr * 64; idx += 256) {
        int i = idx >> 6, j = idx & 63;
        Es[i * 65 + j] = g_E[(size_t)(r0 + i) * NWAY + j];
    }
    /* S = sum of 98 deterministic partials (redundant per CTA) */
    float sp = (tid < NDBLK) ? g_Spart[tid] : 0.f;
    sp = blockSum256(sp);
    if (tid == 0) sS = sp;
    if (tid < 64) vs[tid] = 1.0f;
    if (tid < 3) g_maxd[tid] = 0u;
    __syncthreads();
    if (tid < nr) { wloc[tid] = 1.0f / sS; uprev[tid] = 0.f; }
    __threadfence();
    gridbar();

    int it = 0;
    while (true) {
        int p = it % 3;
        /* t~ = E v ; rows ; w-candidate ; maxdiff */
        float dd = 0.f;
        if (tid < nr) {
            const float* er = Es + tid * 65;
            float tt = 0.f;
#pragma unroll 8
            for (int j = 0; j < 64; j++) tt += er[j] * vs[j];
            float rw = wloc[tid] * tt;
            rowsv[tid] = rw;
            wcand[tid] = 1.0f / tt;
            dd = fabsf(uprev[tid] - rw);
        }
        float m = blockMax256(dd);
        if (tid == 0) atomicMax(&g_maxd[p], __float_as_uint(m));
        /* partial colsums with candidate w (deterministic per-slot order) */
        {
            int j = tid & 63, g = tid >> 6;
            float s = 0.f;
            for (int i = g; i < nr; i += 4) s += Es[i * 65 + j] * wcand[i];
            cred[tid] = s;
            __syncthreads();
            if (tid < 64) {
                float s4 = ((cred[tid] + cred[tid + 64]) + cred[tid + 128]) + cred[tid + 192];
                g_cs[((size_t)p * SGRID + c) * NWAY + tid] = s4;
            }
            if (tid == 0) g_maxd[(p + 1) % 3] = 0u;   /* safe: last read at iter it-2 */
        }
        __threadfence();
        gridbar();
        if (tid == 0) {
            unsigned mb = atomicAdd(&g_maxd[p], 0u);
            sBrk = (__uint_as_float(mb) > EPSF && it < MAXIT) ? 0 : 1;
        }
        __syncthreads();
        if (sBrk) break;
        /* commit body */
        if (tid < nr) { uprev[tid] = rowsv[tid]; wloc[tid] = wcand[tid]; }
        /* v from global partials (fixed order -> deterministic, identical on all CTAs) */
        {
            int j = tid & 63, g = tid >> 6;
            float s = 0.f;
            for (int cc = g; cc < SGRID; cc += 4)
                s += g_cs[((size_t)p * SGRID + cc) * NWAY + j];
            cred[tid] = s;
            __syncthreads();
            if (tid < 64) {
                float s4 = ((cred[tid] + cred[tid + 64]) + cred[tid + 128]) + cred[tid + 192];
                vs[tid] = 195.0f / s4;
            }
            __syncthreads();
        }
        it++;
    }
    if (tid < nr) g_u[r0 + tid] = wloc[tid];
    if (c == 0 && tid < 64) g_v[tid] = vs[tid];
}

/* split-K GEMM: pzpart[s] = (E*w)^T[64 x 960-chunk] @ Z_u-chunk [960 x 1536] */
__global__ void __launch_bounds__(256) k_pz() {
    __shared__ float Ws[32 * 65];
    __shared__ float Zs[32 * 129];
    int t = threadIdx.x;
    int d0 = blockIdx.x * 128;
    int i0 = blockIdx.y * KCH;
    int tj = t & 15, td = t >> 4;
    float acc[4][8];
#pragma unroll
    for (int ii = 0; ii < 4; ii++)
#pragma unroll
        for (int i = 0; i < 8; i++) acc[ii][i] = 0.f;

    for (int kb = 0; kb < KCH; kb += 32) {
        __syncthreads();
#pragma unroll
        for (int l = 0; l < 8; l++) {
            int idx = t + l * 256;
            int j = idx & 63, k = idx >> 6;
            int i = i0 + kb + k;
            Ws[k * 65 + j] = g_E[(size_t)i * NWAY + j] * g_u[i];
        }
#pragma unroll
        for (int l = 0; l < 16; l++) {
            int idx = t + l * 256;
            int d = idx & 127, k = idx >> 7;
            Zs[k * 129 + d] = g_Z[(size_t)(NLAB + i0 + kb + k) * DIM + d0 + d];
        }
        __syncthreads();
#pragma unroll
        for (int k = 0; k < 32; k++) {
            float a[4], b[8];
#pragma unroll
            for (int ii = 0; ii < 4; ii++) a[ii] = Ws[k * 65 + tj * 4 + ii];
#pragma unroll
            for (int i = 0; i < 8; i++) b[i] = Zs[k * 129 + td * 8 + i];
#pragma unroll
            for (int ii = 0; ii < 4; ii++)
#pragma unroll
                for (int i = 0; i < 8; i++) acc[ii][i] += a[ii] * b[i];
        }
    }
#pragma unroll
    for (int ii = 0; ii < 4; ii++)
#pragma unroll
        for (int i = 0; i < 8; i++) {
            int j = tj * 4 + ii, d = d0 + td * 8 + i;
            g_pzpart[((size_t)blockIdx.y * NWAY + j) * DIM + d] = acc[ii][i];
        }
}

/* mus update: deterministic split-K reduce + constant labeled terms */
__global__ void __launch_bounds__(256) k_update() {
    int j = blockIdx.x, t = threadIdx.x;
    float vj = g_v[j];
#pragma unroll
    for (int kk = 0; kk < 6; kk++) {
        int d = t + 256 * kk;
        float s = 0.f;
        for (int ss = 0; ss < KSPLIT; ss++)
            s += g_pzpart[((size_t)ss * NWAY + j) * DIM + d];
        float num = g_SL[d] + EM1F * g_C[j * DIM + d] + vj * s;
        float m = g_mus[j * DIM + d];
        g_mus[j * DIM + d] = m + 0.2f * (num / DENF - m);
    }
}

/* ------------- output ------------- */
__global__ void __launch_bounds__(256) k_outlab(const int* __restrict__ labels,
                                                float* __restrict__ out) {
    int idx = blockIdx.x * 256 + threadIdx.x;   /* < 20480 */
    int r = idx >> 6, j = idx & 63;
    out[idx] = (labels[r] == j) ? 1.0f : 0.0f;
}

__global__ void __launch_bounds__(256) k_outunlab(const int* __restrict__ labels,
                                                  float* __restrict__ out) {
    __shared__ float slv[64];
    int tid = threadIdx.x;
    if (tid < 64) slv[tid] = logf(g_v[tid]);
    __syncthreads();
    int w = tid >> 5, lane = tid & 31;
    int i = blockIdx.x * 8 + w;                 /* < 12480 */
    float lw = logf(g_u[i]);
    float v0 = fmaf(-10.0f, g_D[(size_t)i * NWAY + lane], lw + slv[lane]);
    float v1 = fmaf(-10.0f, g_D[(size_t)i * NWAY + 32 + lane], lw + slv[32 + lane]);
    out[(size_t)(NLAB + i) * NWAY + lane] = v0;
    out[(size_t)(NLAB + i) * NWAY + 32 + lane] = v1;
    float bv = v0; int bi = lane;
    if (v1 > bv) { bv = v1; bi = lane + 32; }
#pragma unroll
    for (int o = 16; o > 0; o >>= 1) {
        float ov = __shfl_down_sync(0xffffffffu, bv, o);
        int   oi = __shfl_down_sync(0xffffffffu, bi, o);
        if (ov > bv || (ov == bv && oi < bi)) { bv = ov; bi = oi; }
    }
    if (lane == 0 && bi == labels[NLAB + i]) atomicAdd(&g_acc, 1);
}

__global__ void k_fin(float* __restrict__ out) {
    if (threadIdx.x == 0) {
        out[(size_t)NTOT * NWAY]     = (float)g_acc / (float)NUNL;
        out[(size_t)NTOT * NWAY + 1] = 0.0f;
    }
}

/* ------------- launch ------------- */
extern "C" void kernel_launch(void* const* d_in, const int* in_sizes, int n_in,
                              void* d_out, int out_size) {
    const float* X      = (const float*)d_in[0];
    const int*   labels = (const int*)d_in[1];
    float*       out    = (float*)d_out;
    (void)in_sizes; (void)n_in; (void)out_size;

    k_setup<<<1, 32>>>();
    k_pownorm<<<NTOT, 256>>>(X);
    k_colpart<<<dim3(6, 32), 256>>>();
    k_colreduce<<<6, 256>>>();
    k_centernorm<<<NTOT, 256>>>();
    k_initmus<<<NWAY, 256>>>();
    k_SL<<<6, 256>>>();

    for (int e = 0; e <= NEPOCH; e++) {
        k_musnorm<<<NWAY, 256>>>();
        k_distE<<<NDBLK, 256>>>();
        k_sinkhorn<<<SGRID, 256>>>();
        if (e < NEPOCH) {
            k_pz<<<dim3(12, KSPLIT), 256>>>();
            k_update<<<NWAY, 256>>>();
        }
    }

    k_outlab<<<80, 256>>>(labels, out);
    k_outunlab<<<1560, 256>>>(labels, out);
    k_fin<<<1, 32>>>(out);
}